// round 1
// baseline (speedup 1.0000x reference)
#include <cuda_runtime.h>
#include <math.h>

#define B_  2
#define S_  2048
#define D_  1024
#define H_  16
#define DK_ 64
#define N_  (B_ * S_)            // 4096 rows
#define BH_ (B_ * H_)            // 32

// ---------------- scratch (static device globals: no allocations) ----------
// layout [b][h][s][dk]
__device__ float g_qp[BH_ * S_ * DK_];   // X @ WQ * scale   (key role)
__device__ float g_kp[BH_ * S_ * DK_];   // X @ WK           (query role)
__device__ float g_vp[BH_ * S_ * DK_];   // X @ WV
__device__ float g_ao[BH_ * S_ * DK_];   // attention output

// ============================================================================
// Kernel 1: QKV projection.  C = X @ W (N x 1024), W selected by blockIdx.z.
// 128x128 tile, K-step 8, 256 threads, 8x8 accum per thread.
// Output scattered into [b][h][s][dk] layout; alpha=0.125 on the Q matrix.
// ============================================================================
#define TM 128
#define TN 128
#define TKK 8

__global__ void __launch_bounds__(256)
proj_qkv_kernel(const float* __restrict__ X,
                const float* __restrict__ WQ,
                const float* __restrict__ WK,
                const float* __restrict__ WV)
{
    const int mat = blockIdx.z;
    const float* __restrict__ W = (mat == 0) ? WQ : (mat == 1) ? WK : WV;
    float* __restrict__ C = (mat == 0) ? g_qp : (mat == 1) ? g_kp : g_vp;
    const float alpha = (mat == 0) ? 0.125f : 1.0f;   // 1/sqrt(64)

    const int row0 = blockIdx.y * TM;
    const int col0 = blockIdx.x * TN;
    const int tid  = threadIdx.x;

    __shared__ float As[TKK][TM];   // transposed A tile
    __shared__ float Bs[TKK][TN];

    float acc[8][8];
#pragma unroll
    for (int i = 0; i < 8; i++)
#pragma unroll
        for (int j = 0; j < 8; j++) acc[i][j] = 0.0f;

    const int tr = (tid >> 4) * 8;   // row offset of this thread's 8x8
    const int tc = (tid & 15) * 8;

    for (int k0 = 0; k0 < D_; k0 += TKK) {
        // A tile: 128 rows x 8 k  (1024 elems / 256 thr = 4 each)
#pragma unroll
        for (int i = 0; i < 4; i++) {
            int idx = tid + i * 256;        // 0..1023
            int r  = idx >> 3;
            int kk = idx & 7;
            As[kk][r] = X[(row0 + r) * D_ + k0 + kk];
        }
        // B tile: 8 k x 128 cols
#pragma unroll
        for (int i = 0; i < 4; i++) {
            int idx = tid + i * 256;
            int kk = idx >> 7;
            int c  = idx & 127;
            Bs[kk][c] = W[(k0 + kk) * D_ + col0 + c];
        }
        __syncthreads();

#pragma unroll
        for (int kk = 0; kk < TKK; kk++) {
            const float4* a4 = reinterpret_cast<const float4*>(&As[kk][tr]);
            const float4* b4 = reinterpret_cast<const float4*>(&Bs[kk][tc]);
            float4 a0 = a4[0], a1 = a4[1];
            float4 b0 = b4[0], b1 = b4[1];
            float a[8] = {a0.x, a0.y, a0.z, a0.w, a1.x, a1.y, a1.z, a1.w};
            float b[8] = {b0.x, b0.y, b0.z, b0.w, b1.x, b1.y, b1.z, b1.w};
#pragma unroll
            for (int i = 0; i < 8; i++)
#pragma unroll
                for (int j = 0; j < 8; j++)
                    acc[i][j] += a[i] * b[j];
        }
        __syncthreads();
    }

    // scatter into [b][h][s][dk]
#pragma unroll
    for (int i = 0; i < 8; i++) {
        int r = row0 + tr + i;
        int b = r >> 11;            // / S_
        int s = r & (S_ - 1);
#pragma unroll
        for (int j = 0; j < 8; j++) {
            int c  = col0 + tc + j;
            int h  = c >> 6;
            int dk = c & 63;
            C[((b * H_ + h) * S_ + s) * DK_ + dk] = acc[i][j] * alpha;
        }
    }
}

// ============================================================================
// Kernel 2: causal flash attention (fp32, online softmax).
//   query role  = g_kp[bh][j][:]
//   key role    = g_qp[bh][i][:]   (already scaled)
//   values      = g_vp[bh][i][:]
//   out[j][d]   = sum_{i<=j} softmax_i(key_i . query_j) * v[i][d]
// Block: 128 threads, 64 queries/tile (2 threads per query, 32 dims each),
// 32 keys per inner tile.
// ============================================================================
#define BQ 64
#define BK 32
#define MASKV (-3.0e38f)

__global__ void __launch_bounds__(128)
attn_kernel()
{
    const int bh = blockIdx.x;                 // 0..31
    const int qt = blockIdx.y;                 // 0..S/64-1
    const float* __restrict__ Kp = g_qp + bh * S_ * DK_;  // key role
    const float* __restrict__ Qp = g_kp + bh * S_ * DK_;  // query role
    const float* __restrict__ Vp = g_vp + bh * S_ * DK_;
    float* __restrict__ Op = g_ao + bh * S_ * DK_;

    const int t    = threadIdx.x;
    const int tq   = t >> 1;          // query within tile
    const int half = t & 1;           // which 32-dim half
    const int j    = qt * BQ + tq;    // global query index

    __shared__ float Ks[BK][DK_];
    __shared__ float Vs[BK][DK_];

    // load this thread's half of the query row
    float4 q4[8];
    {
        const float4* qr = reinterpret_cast<const float4*>(Qp + j * DK_ + half * 32);
#pragma unroll
        for (int d = 0; d < 8; d++) q4[d] = qr[d];
    }

    float4 o4[8];
#pragma unroll
    for (int d = 0; d < 8; d++) o4[d] = make_float4(0.f, 0.f, 0.f, 0.f);
    float m = MASKV, l = 0.0f;

    const int n_kt = 2 * qt + 2;      // key tiles needed (causal)
    for (int kt = 0; kt < n_kt; kt++) {
        // cooperative load of K and V tiles (512 float4 each / 128 threads)
        {
            float4*       Kd = reinterpret_cast<float4*>(&Ks[0][0]);
            float4*       Vd = reinterpret_cast<float4*>(&Vs[0][0]);
            const float4* Ksrc = reinterpret_cast<const float4*>(Kp) + kt * (BK * DK_ / 4);
            const float4* Vsrc = reinterpret_cast<const float4*>(Vp) + kt * (BK * DK_ / 4);
#pragma unroll
            for (int i = 0; i < 4; i++) {
                int f = t + i * 128;
                Kd[f] = Ksrc[f];
                Vd[f] = Vsrc[f];
            }
        }
        __syncthreads();

        // scores for 32 keys (pair-split dot + shfl combine)
        float s[BK];
#pragma unroll
        for (int k = 0; k < BK; k++) {
            const float4* kr = reinterpret_cast<const float4*>(&Ks[k][half * 32]);
            float p = 0.0f;
#pragma unroll
            for (int d = 0; d < 8; d++) {
                float4 kv = kr[d];
                p += q4[d].x * kv.x + q4[d].y * kv.y + q4[d].z * kv.z + q4[d].w * kv.w;
            }
            p += __shfl_xor_sync(0xffffffffu, p, 1);
            int ki = kt * BK + k;
            s[k] = (ki <= j) ? p : MASKV;
        }

        // online softmax update
        float tmax = MASKV;
#pragma unroll
        for (int k = 0; k < BK; k++) tmax = fmaxf(tmax, s[k]);
        float mnew = fmaxf(m, tmax);
        float corr = __expf(m - mnew);     // 0 on the first tile (m = MASKV)
        float psum = 0.0f;
#pragma unroll
        for (int k = 0; k < BK; k++) {
            s[k] = __expf(s[k] - mnew);
            psum += s[k];
        }
        l = l * corr + psum;
#pragma unroll
        for (int d = 0; d < 8; d++) {
            o4[d].x *= corr; o4[d].y *= corr; o4[d].z *= corr; o4[d].w *= corr;
        }
#pragma unroll
        for (int k = 0; k < BK; k++) {
            const float4* vr = reinterpret_cast<const float4*>(&Vs[k][half * 32]);
            float p = s[k];
#pragma unroll
            for (int d = 0; d < 8; d++) {
                float4 vv = vr[d];
                o4[d].x += p * vv.x; o4[d].y += p * vv.y;
                o4[d].z += p * vv.z; o4[d].w += p * vv.w;
            }
        }
        m = mnew;
        __syncthreads();
    }

    const float inv = 1.0f / l;
    float4* orow = reinterpret_cast<float4*>(Op + j * DK_ + half * 32);
#pragma unroll
    for (int d = 0; d < 8; d++) {
        o4[d].x *= inv; o4[d].y *= inv; o4[d].z *= inv; o4[d].w *= inv;
        orow[d] = o4[d];
    }
}

// ============================================================================
// Kernel 3: output projection. out = A @ WO + bO
// A[row = b*S+s][kdim = h*64+v] gathered from g_ao[b][h][s][v].
// ============================================================================
__global__ void __launch_bounds__(256)
out_proj_kernel(const float* __restrict__ WO,
                const float* __restrict__ bO,
                float* __restrict__ out)
{
    const int row0 = blockIdx.y * TM;
    const int col0 = blockIdx.x * TN;
    const int tid  = threadIdx.x;

    __shared__ float As[TKK][TM];
    __shared__ float Bs[TKK][TN];

    float acc[8][8];
#pragma unroll
    for (int i = 0; i < 8; i++)
#pragma unroll
        for (int j = 0; j < 8; j++) acc[i][j] = 0.0f;

    const int tr = (tid >> 4) * 8;
    const int tc = (tid & 15) * 8;

    for (int k0 = 0; k0 < D_; k0 += TKK) {
#pragma unroll
        for (int i = 0; i < 4; i++) {
            int idx = tid + i * 256;
            int r  = idx >> 3;
            int kk = idx & 7;
            int row = row0 + r;
            int b = row >> 11, s = row & (S_ - 1);
            int kg = k0 + kk;
            int h = kg >> 6, v = kg & 63;
            As[kk][r] = g_ao[((b * H_ + h) * S_ + s) * DK_ + v];
        }
#pragma unroll
        for (int i = 0; i < 4; i++) {
            int idx = tid + i * 256;
            int kk = idx >> 7;
            int c  = idx & 127;
            Bs[kk][c] = WO[(k0 + kk) * D_ + col0 + c];
        }
        __syncthreads();

#pragma unroll
        for (int kk = 0; kk < TKK; kk++) {
            const float4* a4 = reinterpret_cast<const float4*>(&As[kk][tr]);
            const float4* b4 = reinterpret_cast<const float4*>(&Bs[kk][tc]);
            float4 a0 = a4[0], a1 = a4[1];
            float4 b0 = b4[0], b1 = b4[1];
            float a[8] = {a0.x, a0.y, a0.z, a0.w, a1.x, a1.y, a1.z, a1.w};
            float b[8] = {b0.x, b0.y, b0.z, b0.w, b1.x, b1.y, b1.z, b1.w};
#pragma unroll
            for (int i = 0; i < 8; i++)
#pragma unroll
                for (int j = 0; j < 8; j++)
                    acc[i][j] += a[i] * b[j];
        }
        __syncthreads();
    }

#pragma unroll
    for (int i = 0; i < 8; i++) {
        int r = row0 + tr + i;
#pragma unroll
        for (int j = 0; j < 8; j++) {
            int c = col0 + tc + j;
            out[r * D_ + c] = acc[i][j] + bO[c];
        }
    }
}

// ============================================================================
// launcher
// inputs (metadata order): 0 inputs(B,S,D) f32, 1 mask (unused, causal),
//                          2 WQ, 3 WK, 4 WV, 5 WO, 6 bO
// ============================================================================
extern "C" void kernel_launch(void* const* d_in, const int* in_sizes, int n_in,
                              void* d_out, int out_size)
{
    (void)in_sizes; (void)n_in; (void)out_size;
    const float* X  = (const float*)d_in[0];
    const float* WQ = (const float*)d_in[2];
    const float* WK = (const float*)d_in[3];
    const float* WV = (const float*)d_in[4];
    const float* WO = (const float*)d_in[5];
    const float* bO = (const float*)d_in[6];
    float* out = (float*)d_out;

    {
        dim3 grid(D_ / TN, N_ / TM, 3);
        proj_qkv_kernel<<<grid, 256>>>(X, WQ, WK, WV);
    }
    {
        dim3 grid(BH_, S_ / BQ);
        attn_kernel<<<grid, 128>>>();
    }
    {
        dim3 grid(D_ / TN, N_ / TM);
        out_proj_kernel<<<grid, 256>>>(WO, bO, out);
    }
}

// round 4
// speedup vs baseline: 4.7492x; 4.7492x over previous
#include <cuda_runtime.h>
#include <stdint.h>

#define B_  2
#define S_  2048
#define D_  1024
#define H_  16
#define DK_ 64
#define N_  (B_ * S_)            // 4096
#define BH_ (B_ * H_)            // 32

// ---------------- scratch (static device globals) ---------------------------
// layout [b][h][s][dk]
__device__ float g_qp[BH_ * S_ * DK_];   // X @ WQ * scale   (key role)
__device__ float g_kp[BH_ * S_ * DK_];   // X @ WK           (query role)
__device__ float g_vp[BH_ * S_ * DK_];   // X @ WV
__device__ float g_ao[BH_ * S_ * DK_];   // attention output

// ---------------- tf32 helpers ----------------------------------------------
__device__ __forceinline__ uint32_t f2tf(float x) {
    uint32_t u; asm("cvt.rna.tf32.f32 %0, %1;" : "=r"(u) : "f"(x)); return u;
}
__device__ __forceinline__ float tf(float x) { return __uint_as_float(f2tf(x)); }

// D += A(16x8) @ B(8x8), tf32 inputs, fp32 accum, accumulate in place.
__device__ __forceinline__ void mma8(float* d, const uint32_t* a, const uint32_t* b) {
    asm volatile("mma.sync.aligned.m16n8k8.row.col.f32.tf32.tf32.f32 "
                 "{%0,%1,%2,%3}, {%4,%5,%6,%7}, {%8,%9}, {%0,%1,%2,%3};\n"
                 : "+f"(d[0]), "+f"(d[1]), "+f"(d[2]), "+f"(d[3])
                 : "r"(a[0]), "r"(a[1]), "r"(a[2]), "r"(a[3]),
                   "r"(b[0]), "r"(b[1]));
}

// ============================================================================
// Kernel 1: QKV projection (tf32 mma). C = X @ W, per blockIdx.z.
// Block tile 128x128, k-tile 32. 8 warps: 2(M) x 4(N), warp tile 64x32.
// ============================================================================
__global__ void __launch_bounds__(256)
proj_qkv_mma(const float* __restrict__ X,
             const float* __restrict__ WQ,
             const float* __restrict__ WK,
             const float* __restrict__ WV)
{
    const int mat = blockIdx.z;
    const float* __restrict__ W = (mat == 0) ? WQ : (mat == 1) ? WK : WV;
    float* __restrict__ C = (mat == 0) ? g_qp : (mat == 1) ? g_kp : g_vp;
    const float alpha = (mat == 0) ? 0.125f : 1.0f;   // 1/sqrt(64)

    const int row0 = blockIdx.y * 128;
    const int col0 = blockIdx.x * 128;
    const int tid  = threadIdx.x;
    const int lane = tid & 31;
    const int wid  = tid >> 5;
    const int wm   = (wid & 1) * 64;     // warp M offset
    const int wn   = (wid >> 1) * 32;    // warp N offset
    const int gr   = lane >> 2;          // group row 0..7
    const int tg   = lane & 3;           // thread-in-group 0..3

    __shared__ float As[128][36];        // [m][k]  (k-tile 32, +4 pad)
    __shared__ float Bs[32][136];        // [k][n]

    float acc[4][4][4];
#pragma unroll
    for (int i = 0; i < 4; i++)
#pragma unroll
        for (int j = 0; j < 4; j++)
#pragma unroll
            for (int r = 0; r < 4; r++) acc[i][j][r] = 0.0f;

    for (int k0 = 0; k0 < D_; k0 += 32) {
        // stage A (128x32) with RNA tf32 rounding
#pragma unroll
        for (int i = 0; i < 4; i++) {
            int f = tid + i * 256;           // 0..1023 float4s
            int r = f >> 3, c = (f & 7) * 4;
            float4 v = *(const float4*)(X + (row0 + r) * D_ + k0 + c);
            As[r][c]     = tf(v.x); As[r][c + 1] = tf(v.y);
            As[r][c + 2] = tf(v.z); As[r][c + 3] = tf(v.w);
        }
        // stage B (32x128)
#pragma unroll
        for (int i = 0; i < 4; i++) {
            int f = tid + i * 256;
            int r = f >> 5, c = (f & 31) * 4;
            float4 v = *(const float4*)(W + (k0 + r) * D_ + col0 + c);
            Bs[r][c]     = tf(v.x); Bs[r][c + 1] = tf(v.y);
            Bs[r][c + 2] = tf(v.z); Bs[r][c + 3] = tf(v.w);
        }
        __syncthreads();

#pragma unroll
        for (int ks = 0; ks < 4; ks++) {
            const int kk = ks * 8;
            uint32_t a[4][4], b[4][2];
#pragma unroll
            for (int mf = 0; mf < 4; mf++) {
                int m = wm + mf * 16;
                a[mf][0] = __float_as_uint(As[m + gr][kk + tg]);
                a[mf][1] = __float_as_uint(As[m + gr + 8][kk + tg]);
                a[mf][2] = __float_as_uint(As[m + gr][kk + tg + 4]);
                a[mf][3] = __float_as_uint(As[m + gr + 8][kk + tg + 4]);
            }
#pragma unroll
            for (int nf = 0; nf < 4; nf++) {
                int n = wn + nf * 8 + gr;
                b[nf][0] = __float_as_uint(Bs[kk + tg][n]);
                b[nf][1] = __float_as_uint(Bs[kk + tg + 4][n]);
            }
#pragma unroll
            for (int mf = 0; mf < 4; mf++)
#pragma unroll
                for (int nf = 0; nf < 4; nf++)
                    mma8(acc[mf][nf], a[mf], b[nf]);
        }
        __syncthreads();
    }

    // epilogue: scatter into [b][h][s][dk]
#pragma unroll
    for (int mf = 0; mf < 4; mf++) {
#pragma unroll
        for (int rr = 0; rr < 2; rr++) {
            int r = row0 + wm + mf * 16 + gr + rr * 8;
            int b = r >> 11, s = r & (S_ - 1);
#pragma unroll
            for (int nf = 0; nf < 4; nf++) {
                int c = col0 + wn + nf * 8 + 2 * tg;
                int h = c >> 6, dk = c & 63;
                float2 v;
                v.x = acc[mf][nf][rr * 2 + 0] * alpha;
                v.y = acc[mf][nf][rr * 2 + 1] * alpha;
                *(float2*)&C[((b * H_ + h) * S_ + s) * DK_ + dk] = v;
            }
        }
    }
}

// ============================================================================
// Kernel 2: causal flash attention, tf32 mma for S=Q@K^T and O=P@V.
// Block: 128 threads (4 warps), 64 queries, 64-key tiles.
// Dynamic smem: Qs/Ks/Vs/Ss each 64x68 floats (full 64-dim head rows).
// ============================================================================
#define MASKV   (-3.0e38f)
#define TW      68                          // tile row stride (64 + 4 pad)
#define TSZ     (64 * TW)                   // floats per tile
#define ATTN_SMEM_BYTES ((4 * TSZ + 128) * 4)

__global__ void __launch_bounds__(128)
attn_mma()
{
    extern __shared__ float dsm[];
    float (*Qs)[TW] = reinterpret_cast<float(*)[TW]>(dsm);
    float (*Ks)[TW] = reinterpret_cast<float(*)[TW]>(dsm + TSZ);
    float (*Vs)[TW] = reinterpret_cast<float(*)[TW]>(dsm + 2 * TSZ);
    float (*Ss)[TW] = reinterpret_cast<float(*)[TW]>(dsm + 3 * TSZ);
    float* s_corr = dsm + 4 * TSZ;
    float* s_l    = s_corr + 64;

    const int bh = blockIdx.x;
    const int qt = (gridDim.y - 1) - blockIdx.y;   // heavy tiles launch first
    const float* __restrict__ Kp = g_qp + bh * S_ * DK_;  // key role (pre-scaled)
    const float* __restrict__ Qp = g_kp + bh * S_ * DK_;  // query role
    const float* __restrict__ Vp = g_vp + bh * S_ * DK_;
    float* __restrict__ Op = g_ao + bh * S_ * DK_;

    const int t    = threadIdx.x;
    const int lane = t & 31;
    const int wid  = t >> 5;
    const int gr   = lane >> 2;
    const int tg   = lane & 3;
    const int wn   = wid * 16;          // warp's 16-col slice (keys / dv)

    // stage Q tile (64x64), tf32-rounded
#pragma unroll
    for (int i = 0; i < 8; i++) {
        int f = t + i * 128;
        int r = f >> 4, c = (f & 15) * 4;
        float4 v = *(const float4*)(Qp + (qt * 64 + r) * DK_ + c);
        Qs[r][c]     = tf(v.x); Qs[r][c + 1] = tf(v.y);
        Qs[r][c + 2] = tf(v.z); Qs[r][c + 3] = tf(v.w);
    }

    float o[4][2][4];
#pragma unroll
    for (int mf = 0; mf < 4; mf++)
#pragma unroll
        for (int nf = 0; nf < 2; nf++)
#pragma unroll
            for (int r = 0; r < 4; r++) o[mf][nf][r] = 0.0f;

    const int srow  = t >> 1;   // softmax row owned by this thread
    const int shalf = t & 1;
    float m = MASKV, l = 0.0f;

    const int nkt = qt + 1;
    for (int kt = 0; kt < nkt; kt++) {
        __syncthreads();   // prev iter's PV done (Ss/Vs free); Q staged
        // stage K and V tiles (64x64 each)
#pragma unroll
        for (int i = 0; i < 8; i++) {
            int f = t + i * 128;
            int r = f >> 4, c = (f & 15) * 4;
            float4 kv = *(const float4*)(Kp + (kt * 64 + r) * DK_ + c);
            Ks[r][c]     = tf(kv.x); Ks[r][c + 1] = tf(kv.y);
            Ks[r][c + 2] = tf(kv.z); Ks[r][c + 3] = tf(kv.w);
            float4 vv = *(const float4*)(Vp + (kt * 64 + r) * DK_ + c);
            Vs[r][c]     = tf(vv.x); Vs[r][c + 1] = tf(vv.y);
            Vs[r][c + 2] = tf(vv.z); Vs[r][c + 3] = tf(vv.w);
        }
        __syncthreads();

        // ---- S = Q @ K^T (warp owns key cols wn..wn+15) ----
        float sacc[4][2][4];
#pragma unroll
        for (int mf = 0; mf < 4; mf++)
#pragma unroll
            for (int nf = 0; nf < 2; nf++)
#pragma unroll
                for (int r = 0; r < 4; r++) sacc[mf][nf][r] = 0.0f;

#pragma unroll
        for (int ks = 0; ks < 8; ks++) {
            const int kk = ks * 8;
            uint32_t a[4][4], b[2][2];
#pragma unroll
            for (int mf = 0; mf < 4; mf++) {
                int mm = mf * 16;
                a[mf][0] = __float_as_uint(Qs[mm + gr][kk + tg]);
                a[mf][1] = __float_as_uint(Qs[mm + gr + 8][kk + tg]);
                a[mf][2] = __float_as_uint(Qs[mm + gr][kk + tg + 4]);
                a[mf][3] = __float_as_uint(Qs[mm + gr + 8][kk + tg + 4]);
            }
#pragma unroll
            for (int nf = 0; nf < 2; nf++) {
                int n = wn + nf * 8 + gr;
                b[nf][0] = __float_as_uint(Ks[n][kk + tg]);
                b[nf][1] = __float_as_uint(Ks[n][kk + tg + 4]);
            }
#pragma unroll
            for (int mf = 0; mf < 4; mf++)
#pragma unroll
                for (int nf = 0; nf < 2; nf++)
                    mma8(sacc[mf][nf], a[mf], b[nf]);
        }

        // store S tile (causal mask on diagonal tile)
        const bool diag = (kt == qt);
#pragma unroll
        for (int mf = 0; mf < 4; mf++) {
#pragma unroll
            for (int rr = 0; rr < 2; rr++) {
                int ri = mf * 16 + gr + rr * 8;
#pragma unroll
                for (int nf = 0; nf < 2; nf++) {
                    int ci = wn + nf * 8 + 2 * tg;
                    float v0 = sacc[mf][nf][rr * 2 + 0];
                    float v1 = sacc[mf][nf][rr * 2 + 1];
                    if (diag) {
                        if (ci > ri)     v0 = MASKV;
                        if (ci + 1 > ri) v1 = MASKV;
                    }
                    Ss[ri][ci]     = v0;
                    Ss[ri][ci + 1] = v1;
                }
            }
        }
        __syncthreads();

        // ---- online softmax: 2 threads per row ----
        {
            float* row = &Ss[srow][shalf * 32];
            float tm = MASKV;
#pragma unroll
            for (int kx = 0; kx < 32; kx++) tm = fmaxf(tm, row[kx]);
            tm = fmaxf(tm, __shfl_xor_sync(0xffffffffu, tm, 1));
            float mnew = fmaxf(m, tm);
            float corr = __expf(m - mnew);
            float ps = 0.0f;
#pragma unroll
            for (int kx = 0; kx < 32; kx++) {
                float e = __expf(row[kx] - mnew);
                ps += e;
                row[kx] = tf(e);
            }
            ps += __shfl_xor_sync(0xffffffffu, ps, 1);
            l = l * corr + ps;
            m = mnew;
            if (shalf == 0) {
                s_corr[srow] = corr;
                if (kt == nkt - 1) s_l[srow] = l;
            }
        }
        __syncthreads();

        // ---- rescale O, then O += P @ V ----
#pragma unroll
        for (int mf = 0; mf < 4; mf++) {
#pragma unroll
            for (int rr = 0; rr < 2; rr++) {
                float c = s_corr[mf * 16 + gr + rr * 8];
#pragma unroll
                for (int nf = 0; nf < 2; nf++) {
                    o[mf][nf][rr * 2 + 0] *= c;
                    o[mf][nf][rr * 2 + 1] *= c;
                }
            }
        }

#pragma unroll
        for (int ks = 0; ks < 8; ks++) {
            const int kk = ks * 8;
            uint32_t a[4][4], b[2][2];
#pragma unroll
            for (int mf = 0; mf < 4; mf++) {
                int mm = mf * 16;
                a[mf][0] = __float_as_uint(Ss[mm + gr][kk + tg]);
                a[mf][1] = __float_as_uint(Ss[mm + gr + 8][kk + tg]);
                a[mf][2] = __float_as_uint(Ss[mm + gr][kk + tg + 4]);
                a[mf][3] = __float_as_uint(Ss[mm + gr + 8][kk + tg + 4]);
            }
#pragma unroll
            for (int nf = 0; nf < 2; nf++) {
                int n = wn + nf * 8 + gr;
                b[nf][0] = __float_as_uint(Vs[kk + tg][n]);
                b[nf][1] = __float_as_uint(Vs[kk + tg + 4][n]);
            }
#pragma unroll
            for (int mf = 0; mf < 4; mf++)
#pragma unroll
                for (int nf = 0; nf < 2; nf++)
                    mma8(o[mf][nf], a[mf], b[nf]);
        }
    }
    __syncthreads();

    // epilogue: normalize and store
#pragma unroll
    for (int mf = 0; mf < 4; mf++) {
#pragma unroll
        for (int rr = 0; rr < 2; rr++) {
            int ri = mf * 16 + gr + rr * 8;
            float linv = 1.0f / s_l[ri];
            int j = qt * 64 + ri;
#pragma unroll
            for (int nf = 0; nf < 2; nf++) {
                int c = wn + nf * 8 + 2 * tg;
                float2 v;
                v.x = o[mf][nf][rr * 2 + 0] * linv;
                v.y = o[mf][nf][rr * 2 + 1] * linv;
                *(float2*)&Op[j * DK_ + c] = v;
            }
        }
    }
}

// ============================================================================
// Kernel 3: output projection (tf32 mma). out = gather(g_ao) @ WO + bO.
// ============================================================================
__global__ void __launch_bounds__(256)
out_proj_mma(const float* __restrict__ WO,
             const float* __restrict__ bO,
             float* __restrict__ out)
{
    const int row0 = blockIdx.y * 128;
    const int col0 = blockIdx.x * 128;
    const int tid  = threadIdx.x;
    const int lane = tid & 31;
    const int wid  = tid >> 5;
    const int wm   = (wid & 1) * 64;
    const int wn   = (wid >> 1) * 32;
    const int gr   = lane >> 2;
    const int tg   = lane & 3;

    __shared__ float As[128][36];
    __shared__ float Bs[32][136];

    float acc[4][4][4];
#pragma unroll
    for (int i = 0; i < 4; i++)
#pragma unroll
        for (int j = 0; j < 4; j++)
#pragma unroll
            for (int r = 0; r < 4; r++) acc[i][j][r] = 0.0f;

    for (int k0 = 0; k0 < D_; k0 += 32) {
        // gather A from head-interleaved attention output
#pragma unroll
        for (int i = 0; i < 4; i++) {
            int f = tid + i * 256;
            int r = f >> 3, c = (f & 7) * 4;
            int row = row0 + r;
            int b = row >> 11, s = row & (S_ - 1);
            int kg = k0 + c;
            int h = kg >> 6, v = kg & 63;
            float4 av = *(const float4*)&g_ao[((b * H_ + h) * S_ + s) * DK_ + v];
            As[r][c]     = tf(av.x); As[r][c + 1] = tf(av.y);
            As[r][c + 2] = tf(av.z); As[r][c + 3] = tf(av.w);
        }
#pragma unroll
        for (int i = 0; i < 4; i++) {
            int f = tid + i * 256;
            int r = f >> 5, c = (f & 31) * 4;
            float4 v = *(const float4*)(WO + (k0 + r) * D_ + col0 + c);
            Bs[r][c]     = tf(v.x); Bs[r][c + 1] = tf(v.y);
            Bs[r][c + 2] = tf(v.z); Bs[r][c + 3] = tf(v.w);
        }
        __syncthreads();

#pragma unroll
        for (int ks = 0; ks < 4; ks++) {
            const int kk = ks * 8;
            uint32_t a[4][4], b[4][2];
#pragma unroll
            for (int mf = 0; mf < 4; mf++) {
                int mmm = wm + mf * 16;
                a[mf][0] = __float_as_uint(As[mmm + gr][kk + tg]);
                a[mf][1] = __float_as_uint(As[mmm + gr + 8][kk + tg]);
                a[mf][2] = __float_as_uint(As[mmm + gr][kk + tg + 4]);
                a[mf][3] = __float_as_uint(As[mmm + gr + 8][kk + tg + 4]);
            }
#pragma unroll
            for (int nf = 0; nf < 4; nf++) {
                int n = wn + nf * 8 + gr;
                b[nf][0] = __float_as_uint(Bs[kk + tg][n]);
                b[nf][1] = __float_as_uint(Bs[kk + tg + 4][n]);
            }
#pragma unroll
            for (int mf = 0; mf < 4; mf++)
#pragma unroll
                for (int nf = 0; nf < 4; nf++)
                    mma8(acc[mf][nf], a[mf], b[nf]);
        }
        __syncthreads();
    }

#pragma unroll
    for (int mf = 0; mf < 4; mf++) {
#pragma unroll
        for (int rr = 0; rr < 2; rr++) {
            int r = row0 + wm + mf * 16 + gr + rr * 8;
#pragma unroll
            for (int nf = 0; nf < 4; nf++) {
                int c = col0 + wn + nf * 8 + 2 * tg;
                float2 v;
                v.x = acc[mf][nf][rr * 2 + 0] + bO[c];
                v.y = acc[mf][nf][rr * 2 + 1] + bO[c + 1];
                *(float2*)&out[r * D_ + c] = v;
            }
        }
    }
}

// ============================================================================
// launcher — inputs: 0 X, 1 mask(unused), 2 WQ, 3 WK, 4 WV, 5 WO, 6 bO
// ============================================================================
extern "C" void kernel_launch(void* const* d_in, const int* in_sizes, int n_in,
                              void* d_out, int out_size)
{
    (void)in_sizes; (void)n_in; (void)out_size;
    const float* X  = (const float*)d_in[0];
    const float* WQ = (const float*)d_in[2];
    const float* WK = (const float*)d_in[3];
    const float* WV = (const float*)d_in[4];
    const float* WO = (const float*)d_in[5];
    const float* bO = (const float*)d_in[6];
    float* out = (float*)d_out;

    // one-time attribute setup (not a stream op; safe under graph capture,
    // but keep the captured call path to pure kernel launches anyway)
    static bool s_init = false;
    if (!s_init) {
        cudaFuncSetAttribute(attn_mma,
                             cudaFuncAttributeMaxDynamicSharedMemorySize,
                             ATTN_SMEM_BYTES);
        s_init = true;
    }

    {
        dim3 grid(D_ / 128, N_ / 128, 3);
        proj_qkv_mma<<<grid, 256>>>(X, WQ, WK, WV);
    }
    {
        dim3 grid(BH_, S_ / 64);
        attn_mma<<<grid, 128, ATTN_SMEM_BYTES>>>();
    }
    {
        dim3 grid(D_ / 128, N_ / 128);
        out_proj_mma<<<grid, 256>>>(WO, bO, out);
    }
}